// round 15
// baseline (speedup 1.0000x reference)
#include <cuda_runtime.h>

#define H1   1000
#define NCH1 1344     // layer-1 row chunks
#define RPC1 25       // rows per chunk (1344*25 = 33600)

#define NS   307      // needed layer-2 columns (x2[15k+1])
#define KC2  40       // layer-2 k chunks
#define RPC2 25       // rows per chunk (40*25 = 1000)

#define S1O  5121     // seg1 output cols
#define S1SZ 81936    // 16 * 5121
#define KT1  3        // seg1 k-split across blocks
#define KPB  168      // k per block (3*168 = 504 >= 500)
#define KPW  21       // k per warp (8*21 = 168)

// ---------------- scratch (__device__ globals; no allocations) ----------------
__device__ float g_part1[NCH1 * H1];         // layer-1 partial sums [chunk][j]
__device__ float g_part2[KC2 * 320];         // layer-2 partials for the 307 scalars
__device__ float g_sp1[KT1 * S1SZ];          // seg1 k-split partials

// ---------------- layer 1: partial GEMV, 1344 blocks x 256 thr ---------------
__global__ void __launch_bounds__(256) k_l1_partial(const float* __restrict__ x,
                                                    const float* __restrict__ W) {
    __shared__ float xs[RPC1];
    int bx = blockIdx.x, tid = threadIdx.x;
    int i0 = bx * RPC1;
    if (tid < RPC1) xs[tid] = x[i0 + tid];
    __syncthreads();
    if (tid < 250) {
        const float4* W4 = (const float4*)W;   // 1000 floats/row = 250 float4
        float4 a = make_float4(0.f, 0.f, 0.f, 0.f);
        #pragma unroll
        for (int r = 0; r < RPC1; ++r) {
            float4 w = __ldcs(&W4[(size_t)(i0 + r) * 250 + tid]);
            float xv = xs[r];
            a.x = fmaf(xv, w.x, a.x);
            a.y = fmaf(xv, w.y, a.y);
            a.z = fmaf(xv, w.z, a.z);
            a.w = fmaf(xv, w.w, a.w);
        }
        ((float4*)g_part1)[bx * 250 + tid] = a;
    }
}

// -------- mid: fold layer-1 partials -> h1 (shared), then layer-2 partials ---
__global__ void __launch_bounds__(512) k_mid(const float* __restrict__ bd1,
                                             const float* __restrict__ Wd2) {
    __shared__ float red[400];
    __shared__ float hs[RPC2];
    int tid = threadIdx.x, bx = blockIdx.x;
    int i0 = bx * RPC2;

    if (tid < 400) {                           // 25 rows x 16 chunk-groups
        int jj = tid % 25, g = tid / 25;
        float v = 0.f;
        int c0 = g * 84;                       // 1344/16
        #pragma unroll 12
        for (int c = 0; c < 84; ++c)
            v += g_part1[(c0 + c) * H1 + i0 + jj];
        red[tid] = v;
    }
    __syncthreads();
    if (tid < RPC2) {
        float s = bd1[i0 + tid];
        #pragma unroll
        for (int g = 0; g < 16; ++g) s += red[g * 25 + tid];
        hs[tid] = fmaxf(s, 0.f);
    }
    __syncthreads();
    if (tid < NS) {
        float acc = 0.f;
        const float* base = Wd2 + (size_t)i0 * 4605 + 15 * tid + 1;
        #pragma unroll
        for (int r = 0; r < RPC2; ++r)
            acc = fmaf(hs[r], base[(size_t)r * 4605], acc);
        g_part2[bx * 320 + tid] = acc;
    }
}

// ---------------- shared helpers ---------------------------------------------
__device__ __forceinline__ void fold_scalars(float* s_sh, const float* __restrict__ bd2,
                                             int sbase, int JB) {
    int tid = threadIdx.x;
    if (tid < JB) {
        int ks = sbase + tid;
        float v = bd2[15 * ks + 1];
        #pragma unroll
        for (int c = 0; c < KC2; ++c) v += g_part2[c * 320 + ks];
        s_sh[tid] = fmaxf(v, 0.f);
    }
}

// ---- seg1 stage 1: 483 blocks = 161 col-tiles x 3 k-chunks ------------------
__global__ void __launch_bounds__(256) k_seg1(
    const float* __restrict__ bd2,
    const float* __restrict__ Wa, const float* __restrict__ ba,
    const float* __restrict__ Wb)
{
    __shared__ float s_sh[16];
    __shared__ float h_sh[KPB * 16];           // [kl][j]
    __shared__ float red[8 * 512];
    int tid = threadIdx.x;
    int ct = blockIdx.x % 161, kt = blockIdx.x / 161;
    int kbase = kt * KPB;

    fold_scalars(s_sh, bd2, 0, 16);
    __syncthreads();

    for (int kl = tid; kl < KPB; kl += 256) {
        int k = kbase + kl;
        float av = 0.f, bv = 0.f;
        if (k < 500) { av = Wa[k]; bv = ba[k]; }
        float* hk = &h_sh[kl * 16];
        #pragma unroll
        for (int j = 0; j < 16; ++j) {
            float v = (k < 500) ? fmaxf(fmaf(s_sh[j], av, bv), 0.f) : 0.f;
            hk[j] = v;
        }
    }
    __syncthreads();

    int w = tid >> 5, lane = tid & 31;
    int n = ct * 32 + lane;
    bool nok = (n < S1O);
    int kl0 = w * KPW;
    int k0 = kbase + kl0;

    float acc[16];
    #pragma unroll
    for (int j = 0; j < 16; ++j) acc[j] = 0.f;

    #pragma unroll
    for (int b = 0; b < 3; ++b) {
        float wv[7];
        #pragma unroll
        for (int r = 0; r < 7; ++r) {
            int k = k0 + b * 7 + r;
            wv[r] = (nok && k < 500) ? Wb[(size_t)k * S1O + n] : 0.f;
        }
        #pragma unroll
        for (int r = 0; r < 7; ++r) {
            const float* hr = &h_sh[(kl0 + b * 7 + r) * 16];
            #pragma unroll
            for (int j = 0; j < 16; ++j)
                acc[j] = fmaf(hr[j], wv[r], acc[j]);
        }
    }

    #pragma unroll
    for (int j = 0; j < 16; ++j)
        red[w * 512 + j * 32 + lane] = acc[j];
    __syncthreads();

    #pragma unroll
    for (int p = tid; p < 512; p += 256) {
        int j = p >> 5, ln = p & 31;
        int nn = ct * 32 + ln;
        if (nn < S1O) {
            float v = 0.f;
            #pragma unroll
            for (int ww = 0; ww < 8; ++ww) v += red[ww * 512 + p];
            g_sp1[kt * S1SZ + j * S1O + nn] = v;
        }
    }
}

// ---- staged segment: Wb chunks go through smem (coalesced, batched LDG) -----
// Block: JB scalars x col slice [c0, c0+256*CPT), K=100 in 5 chunks of 20 rows.
template<int JB, int CPT>
__device__ __forceinline__ void seg_staged(
    float* smem, float* __restrict__ out, const float* __restrict__ bd2,
    const float* __restrict__ Wa, const float* __restrict__ ba,
    const float* __restrict__ Wb, const float* __restrict__ bb,
    int O, int sbase, int jg0, int c0)
{
    float* s_sh = smem;                        // [16]
    float* h_sh = smem + 16;                   // [100][JB]
    float* wst  = smem + 16 + 100 * JB;        // [20][CW]
    int tid = threadIdx.x;
    int CW = min(256 * CPT, O - c0);

    fold_scalars(s_sh, bd2, sbase + jg0, JB);
    __syncthreads();

    if (tid < 100) {
        float av = Wa[tid], bv = ba[tid];
        float* hk = &h_sh[tid * JB];
        #pragma unroll
        for (int j = 0; j < JB; ++j)
            hk[j] = fmaxf(fmaf(s_sh[j], av, bv), 0.f);
    }

    float acc[JB * CPT];
    #pragma unroll
    for (int i = 0; i < JB * CPT; ++i) acc[i] = 0.f;

    #pragma unroll
    for (int cc = 0; cc < 5; ++cc) {
        __syncthreads();                       // h ready (cc=0) / prev compute done
        // stage 20 rows x CW cols, coalesced, independent addresses
        #pragma unroll
        for (int r = 0; r < 20; ++r) {
            const float* wrow = Wb + (size_t)(cc * 20 + r) * O + c0;
            for (int c = tid; c < CW; c += 256)
                wst[r * CW + c] = wrow[c];
        }
        __syncthreads();
        #pragma unroll
        for (int r = 0; r < 20; ++r) {
            float w0 = (tid < CW) ? wst[r * CW + tid] : 0.f;
            float w1 = 0.f;
            if (CPT == 2 && tid + 256 < CW) w1 = wst[r * CW + tid + 256];
            const float* hr = &h_sh[(cc * 20 + r) * JB];
            #pragma unroll
            for (int j = 0; j < JB; ++j) {
                acc[j * CPT] = fmaf(hr[j], w0, acc[j * CPT]);
                if (CPT == 2) acc[j * CPT + 1] = fmaf(hr[j], w1, acc[j * CPT + 1]);
            }
        }
    }

    #pragma unroll
    for (int j = 0; j < JB; ++j) {
        #pragma unroll
        for (int c = 0; c < CPT; ++c) {
            int n = c0 + c * 256 + tid;
            if (c * 256 + tid < CW)
                out[(size_t)(jg0 + j) * O + n] = fmaxf(acc[j * CPT + c] + bb[n], 0.f);
        }
    }
}

// ---- finish: seg1 fold (321) + seg3 (64) + seg2 (8) + seg4 (7) --------------
// smem: 16 + 400 (h) + 20*512 (stage) = 10656 floats = 42.6 KB
__global__ void __launch_bounds__(256) k_finish(
    float* __restrict__ out,
    const float* __restrict__ bd2, const float* __restrict__ b1b,
    const float* __restrict__ W2a, const float* __restrict__ b2a, const float* __restrict__ W2b, const float* __restrict__ b2b,
    const float* __restrict__ W3a, const float* __restrict__ b3a, const float* __restrict__ W3b, const float* __restrict__ b3b,
    const float* __restrict__ W4a, const float* __restrict__ b4a, const float* __restrict__ W4b, const float* __restrict__ b4b)
{
    __shared__ float smem[10656];
    int b = blockIdx.x, tid = threadIdx.x;
    if (b < 321) {                             // seg1 fold: coalesced, MLP=3
        int idx = b * 256 + tid;
        if (idx < S1SZ) {
            int n = idx % S1O;
            float v = b1b[n] + g_sp1[idx] + g_sp1[S1SZ + idx] + g_sp1[2 * S1SZ + idx];
            out[idx] = fmaxf(v, 0.f);
        }
    } else if (b < 385) {
        int jb = b - 321;
        seg_staged<4, 2>(smem, out + 90160, bd2, W3a, b3a, W3b, b3b, 321, 48, jb * 4, 0);
    } else if (b < 393) {
        int jb = b - 385;
        seg_staged<4, 2>(smem, out + 81936, bd2, W2a, b2a, W2b, b2b, 257, 16, jb * 4, 0);
    } else {
        int ct = b - 393;
        seg_staged<3, 1>(smem, out + 172336, bd2, W4a, b4a, W4b, b4b, 1542, 304, 0, ct * 256);
    }
}

extern "C" void kernel_launch(void* const* d_in, const int* in_sizes, int n_in,
                              void* d_out, int out_size) {
    const float* x   = (const float*)d_in[0];
    const float* Wd1 = (const float*)d_in[1];
    const float* bd1 = (const float*)d_in[2];
    const float* Wd2 = (const float*)d_in[3];
    const float* bd2 = (const float*)d_in[4];
    const float* W1a = (const float*)d_in[5];
    const float* b1a = (const float*)d_in[6];
    const float* W1b = (const float*)d_in[7];
    const float* b1b = (const float*)d_in[8];
    const float* W2a = (const float*)d_in[9];
    const float* b2a = (const float*)d_in[10];
    const float* W2b = (const float*)d_in[11];
    const float* b2b = (const float*)d_in[12];
    const float* W3a = (const float*)d_in[13];
    const float* b3a = (const float*)d_in[14];
    const float* W3b = (const float*)d_in[15];
    const float* b3b = (const float*)d_in[16];
    const float* W4a = (const float*)d_in[17];
    const float* b4a = (const float*)d_in[18];
    const float* W4b = (const float*)d_in[19];
    const float* b4b = (const float*)d_in[20];
    float* out = (float*)d_out;

    k_l1_partial<<<NCH1, 256>>>(x, Wd1);
    k_mid<<<KC2, 512>>>(bd1, Wd2);
    k_seg1<<<161 * KT1, 256>>>(bd2, W1a, b1a, W1b);
    k_finish<<<400, 256>>>(out, bd2, b1b,
                           W2a, b2a, W2b, b2b,
                           W3a, b3a, W3b, b3b,
                           W4a, b4a, W4b, b4b);
}

// round 16
// speedup vs baseline: 1.8060x; 1.8060x over previous
#include <cuda_runtime.h>

#define H1   1000
#define NCH1 1344     // layer-1 row chunks
#define RPC1 25       // rows per chunk (1344*25 = 33600)

#define NS   307      // needed layer-2 columns (x2[15k+1])
#define KC2  40       // layer-2 k chunks
#define RPC2 25       // rows per chunk (40*25 = 1000)

#define S1O  5121     // seg1 output cols
#define S1SZ 81936    // 16 * 5121
#define KT1  3        // seg1 k-split across blocks
#define KPB  168      // k per block (3*168 = 504 >= 500)
#define KPW  21       // k per warp (8*21 = 168)

// ---------------- scratch (__device__ globals; no allocations) ----------------
__device__ float g_part1[NCH1 * H1];         // layer-1 partial sums [chunk][j]
__device__ float g_part2[KC2 * 320];         // layer-2 partials for the 307 scalars
__device__ float g_sp1[KT1 * S1SZ];          // seg1 k-split partials

// ---------------- layer 1: partial GEMV, 1344 blocks x 256 thr ---------------
__global__ void __launch_bounds__(256) k_l1_partial(const float* __restrict__ x,
                                                    const float* __restrict__ W) {
    __shared__ float xs[RPC1];
    int bx = blockIdx.x, tid = threadIdx.x;
    int i0 = bx * RPC1;
    if (tid < RPC1) xs[tid] = x[i0 + tid];
    __syncthreads();
    if (tid < 250) {
        const float4* W4 = (const float4*)W;   // 1000 floats/row = 250 float4
        float4 a = make_float4(0.f, 0.f, 0.f, 0.f);
        #pragma unroll
        for (int r = 0; r < RPC1; ++r) {
            float4 w = __ldcs(&W4[(size_t)(i0 + r) * 250 + tid]);
            float xv = xs[r];
            a.x = fmaf(xv, w.x, a.x);
            a.y = fmaf(xv, w.y, a.y);
            a.z = fmaf(xv, w.z, a.z);
            a.w = fmaf(xv, w.w, a.w);
        }
        ((float4*)g_part1)[bx * 250 + tid] = a;
    }
}

// -------- mid: fold layer-1 partials -> h1 (shared), then layer-2 partials ---
__global__ void __launch_bounds__(512) k_mid(const float* __restrict__ bd1,
                                             const float* __restrict__ Wd2) {
    __shared__ float red[400];
    __shared__ float hs[RPC2];
    int tid = threadIdx.x, bx = blockIdx.x;
    int i0 = bx * RPC2;

    if (tid < 400) {                           // 25 rows x 16 chunk-groups
        int jj = tid % 25, g = tid / 25;
        float v = 0.f;
        int c0 = g * 84;                       // 1344/16
        #pragma unroll 12
        for (int c = 0; c < 84; ++c)
            v += g_part1[(c0 + c) * H1 + i0 + jj];
        red[tid] = v;
    }
    __syncthreads();
    if (tid < RPC2) {
        float s = bd1[i0 + tid];
        #pragma unroll
        for (int g = 0; g < 16; ++g) s += red[g * 25 + tid];
        hs[tid] = fmaxf(s, 0.f);
    }
    __syncthreads();
    if (tid < NS) {
        float acc = 0.f;
        const float* base = Wd2 + (size_t)i0 * 4605 + 15 * tid + 1;
        #pragma unroll
        for (int r = 0; r < RPC2; ++r)
            acc = fmaf(hs[r], base[(size_t)r * 4605], acc);
        g_part2[bx * 320 + tid] = acc;
    }
}

// ---------------- shared helpers ---------------------------------------------
__device__ __forceinline__ void fold_scalars(float* s_sh, const float* __restrict__ bd2,
                                             int sbase, int JB) {
    int tid = threadIdx.x;
    if (tid < JB) {
        int ks = sbase + tid;
        float v = bd2[15 * ks + 1];
        #pragma unroll
        for (int c = 0; c < KC2; ++c) v += g_part2[c * 320 + ks];
        s_sh[tid] = fmaxf(v, 0.f);
    }
}

// ---- seg1 stage 1: 483 blocks = 161 col-tiles x 3 k-chunks ------------------
__global__ void __launch_bounds__(256) k_seg1(
    const float* __restrict__ bd2,
    const float* __restrict__ Wa, const float* __restrict__ ba,
    const float* __restrict__ Wb)
{
    __shared__ float s_sh[16];
    __shared__ float h_sh[KPB * 16];           // [kl][j]
    __shared__ float red[8 * 512];
    int tid = threadIdx.x;
    int ct = blockIdx.x % 161, kt = blockIdx.x / 161;
    int kbase = kt * KPB;

    fold_scalars(s_sh, bd2, 0, 16);
    __syncthreads();

    for (int kl = tid; kl < KPB; kl += 256) {
        int k = kbase + kl;
        float av = 0.f, bv = 0.f;
        if (k < 500) { av = Wa[k]; bv = ba[k]; }
        float* hk = &h_sh[kl * 16];
        #pragma unroll
        for (int j = 0; j < 16; ++j) {
            float v = (k < 500) ? fmaxf(fmaf(s_sh[j], av, bv), 0.f) : 0.f;
            hk[j] = v;
        }
    }
    __syncthreads();

    int w = tid >> 5, lane = tid & 31;
    int n = ct * 32 + lane;
    bool nok = (n < S1O);
    int kl0 = w * KPW;
    int k0 = kbase + kl0;

    float acc[16];
    #pragma unroll
    for (int j = 0; j < 16; ++j) acc[j] = 0.f;

    #pragma unroll
    for (int b = 0; b < 3; ++b) {
        float wv[7];
        #pragma unroll
        for (int r = 0; r < 7; ++r) {
            int k = k0 + b * 7 + r;
            wv[r] = (nok && k < 500) ? Wb[(size_t)k * S1O + n] : 0.f;
        }
        #pragma unroll
        for (int r = 0; r < 7; ++r) {
            const float* hr = &h_sh[(kl0 + b * 7 + r) * 16];
            #pragma unroll
            for (int j = 0; j < 16; ++j)
                acc[j] = fmaf(hr[j], wv[r], acc[j]);
        }
    }

    #pragma unroll
    for (int j = 0; j < 16; ++j)
        red[w * 512 + j * 32 + lane] = acc[j];
    __syncthreads();

    #pragma unroll
    for (int p = tid; p < 512; p += 256) {
        int j = p >> 5, ln = p & 31;
        int nn = ct * 32 + ln;
        if (nn < S1O) {
            float v = 0.f;
            #pragma unroll
            for (int ww = 0; ww < 8; ++ww) v += red[ww * 512 + p];
            g_sp1[kt * S1SZ + j * S1O + nn] = v;
        }
    }
}

// ---- small segment: 32 cols x JB scalars per block, 8-warp k-split K=100 ----
// Per warp: 13 independent coalesced LDGs (k = w*13 + r), smem reduce, final write.
template<int JB>
__device__ __forceinline__ void seg_small(
    float* smem, float* __restrict__ out, const float* __restrict__ bd2,
    const float* __restrict__ Wa, const float* __restrict__ ba,
    const float* __restrict__ Wb, const float* __restrict__ bb,
    int O, int sbase, int jg0, int ct)
{
    float* s_sh = smem;                        // [16]
    float* h_sh = smem + 16;                   // [104][JB] (k >= 100 zero-padded)
    float* red  = smem + 16 + 104 * JB;        // [8][JB][32]
    int tid = threadIdx.x;

    fold_scalars(s_sh, bd2, sbase + jg0, JB);
    __syncthreads();

    if (tid < 104) {
        float av = 0.f, bv = 0.f;
        if (tid < 100) { av = Wa[tid]; bv = ba[tid]; }
        float* hk = &h_sh[tid * JB];
        #pragma unroll
        for (int j = 0; j < JB; ++j)
            hk[j] = (tid < 100) ? fmaxf(fmaf(s_sh[j], av, bv), 0.f) : 0.f;
    }
    __syncthreads();

    int w = tid >> 5, lane = tid & 31;
    int n = ct * 32 + lane;
    bool nok = (n < O);
    int k0 = w * 13;                           // max k = 7*13+12 = 103 < 104

    float wv[13];
    #pragma unroll
    for (int r = 0; r < 13; ++r) {
        int k = k0 + r;
        wv[r] = (nok && k < 100) ? Wb[(size_t)k * O + n] : 0.f;
    }

    float acc[JB];
    #pragma unroll
    for (int j = 0; j < JB; ++j) acc[j] = 0.f;
    #pragma unroll
    for (int r = 0; r < 13; ++r) {
        const float* hr = &h_sh[(k0 + r) * JB];
        #pragma unroll
        for (int j = 0; j < JB; ++j)
            acc[j] = fmaf(hr[j], wv[r], acc[j]);
    }

    #pragma unroll
    for (int j = 0; j < JB; ++j)
        red[(w * JB + j) * 32 + lane] = acc[j];
    __syncthreads();

    for (int p = tid; p < JB * 32; p += 256) {
        int j = p >> 5, ln = p & 31;
        int nn = ct * 32 + ln;
        if (nn < O) {
            float v = bb[nn];
            #pragma unroll
            for (int ww = 0; ww < 8; ++ww) v += red[(ww * JB + j) * 32 + ln];
            out[(size_t)(jg0 + j) * O + nn] = fmaxf(v, 0.f);
        }
    }
}

// ---- finish: seg1 fold (321) + seg3 (704) + seg2 (72) + seg4 (49) -----------
// smem: 16 + 104*4 + 8*4*32 = 1456 floats = 5.8 KB
__global__ void __launch_bounds__(256) k_finish(
    float* __restrict__ out,
    const float* __restrict__ bd2, const float* __restrict__ b1b,
    const float* __restrict__ W2a, const float* __restrict__ b2a, const float* __restrict__ W2b, const float* __restrict__ b2b,
    const float* __restrict__ W3a, const float* __restrict__ b3a, const float* __restrict__ W3b, const float* __restrict__ b3b,
    const float* __restrict__ W4a, const float* __restrict__ b4a, const float* __restrict__ W4b, const float* __restrict__ b4b)
{
    __shared__ float smem[1456];
    int b = blockIdx.x, tid = threadIdx.x;
    if (b < 321) {                             // seg1 fold: coalesced, MLP=3
        int idx = b * 256 + tid;
        if (idx < S1SZ) {
            int n = idx % S1O;
            float v = b1b[n] + g_sp1[idx] + g_sp1[S1SZ + idx] + g_sp1[2 * S1SZ + idx];
            out[idx] = fmaxf(v, 0.f);
        }
    } else if (b < 1025) {                     // seg3: 64 j-tiles x 11 col-tiles
        int l = b - 321;
        int jt = l / 11, ct = l % 11;
        seg_small<4>(smem, out + 90160, bd2, W3a, b3a, W3b, b3b, 321, 48, jt * 4, ct);
    } else if (b < 1097) {                     // seg2: 8 j-tiles x 9 col-tiles
        int l = b - 1025;
        int jt = l / 9, ct = l % 9;
        seg_small<4>(smem, out + 81936, bd2, W2a, b2a, W2b, b2b, 257, 16, jt * 4, ct);
    } else {                                   // seg4: 49 col-tiles
        int ct = b - 1097;
        seg_small<3>(smem, out + 172336, bd2, W4a, b4a, W4b, b4b, 1542, 304, 0, ct);
    }
}

extern "C" void kernel_launch(void* const* d_in, const int* in_sizes, int n_in,
                              void* d_out, int out_size) {
    const float* x   = (const float*)d_in[0];
    const float* Wd1 = (const float*)d_in[1];
    const float* bd1 = (const float*)d_in[2];
    const float* Wd2 = (const float*)d_in[3];
    const float* bd2 = (const float*)d_in[4];
    const float* W1a = (const float*)d_in[5];
    const float* b1a = (const float*)d_in[6];
    const float* W1b = (const float*)d_in[7];
    const float* b1b = (const float*)d_in[8];
    const float* W2a = (const float*)d_in[9];
    const float* b2a = (const float*)d_in[10];
    const float* W2b = (const float*)d_in[11];
    const float* b2b = (const float*)d_in[12];
    const float* W3a = (const float*)d_in[13];
    const float* b3a = (const float*)d_in[14];
    const float* W3b = (const float*)d_in[15];
    const float* b3b = (const float*)d_in[16];
    const float* W4a = (const float*)d_in[17];
    const float* b4a = (const float*)d_in[18];
    const float* W4b = (const float*)d_in[19];
    const float* b4b = (const float*)d_in[20];
    float* out = (float*)d_out;

    k_l1_partial<<<NCH1, 256>>>(x, Wd1);
    k_mid<<<KC2, 512>>>(bd1, Wd2);
    k_seg1<<<161 * KT1, 256>>>(bd2, W1a, b1a, W1b);
    k_finish<<<1146, 256>>>(out, bd2, b1b,
                            W2a, b2a, W2b, b2b,
                            W3a, b3a, W3b, b3b,
                            W4a, b4a, W4b, b4b);
}